// round 14
// baseline (speedup 1.0000x reference)
#include <cuda_runtime.h>
#include <cuda_fp16.h>
#include <cstdint>
#include <math_constants.h>

// ============================================================================
// QKV_Attention via mma.sync m16n8k16 fp16 (f32 acc) + ldmatrix.
// Round 14: R13 champion (PDL everywhere) + merged prep: the xsa
// convert+transpose and the Wq convert run as one grid (z=0..3: xsa batches,
// z=4: Wq) -> one PDL node fewer, prep halves run concurrently.
// ============================================================================

#define NTHREADS 256
#define BK 64
#define TILEB 16384                 // 128 rows x 128B
#define STAGEB (2*TILEB)            // A + B
#define NSTAGE 3
#define DSMEMB (NSTAGE*STAGEB)      // 98304

__device__ __half g_qh [4096UL*4096UL];      // 32 MB
__device__ __half g_xh [4UL*1024UL*512UL];   //  4 MB
__device__ __half g_wh [4096UL*512UL];       //  4 MB
__device__ __half g_xth[4UL*512UL*1024UL];   //  4 MB
__device__ __half g_ph [32768UL*1024UL];     // 64 MB

// ---------------------------------------------------------------- helpers
#define GDC_WAIT()   asm volatile("griddepcontrol.wait;" ::: "memory")
#define GDC_LAUNCH() asm volatile("griddepcontrol.launch_dependents;" ::: "memory")

__device__ __forceinline__ uint32_t smem_u32(const void* p) {
    uint32_t a;
    asm("{ .reg .u64 t; cvta.to.shared.u64 t, %1; cvt.u32.u64 %0, t; }"
        : "=r"(a) : "l"(p));
    return a;
}
#define CP16(d, s) \
    asm volatile("cp.async.cg.shared.global [%0], [%1], 16;" :: "r"(d), "l"(s))
#define CP_COMMIT() asm volatile("cp.async.commit_group;" ::: "memory")
#define CP_WAIT1()  asm volatile("cp.async.wait_group 1;" ::: "memory")

#define LDSM4(r, a) \
    asm volatile("ldmatrix.sync.aligned.m8n8.x4.shared.b16 {%0,%1,%2,%3}, [%4];" \
        : "=r"((r)[0]), "=r"((r)[1]), "=r"((r)[2]), "=r"((r)[3]) : "r"(a))

__device__ __forceinline__ void mma_f16(float c[4], const uint32_t a[4],
                                        uint32_t b0, uint32_t b1) {
    asm volatile(
        "mma.sync.aligned.m16n8k16.row.col.f32.f16.f16.f32 "
        "{%0,%1,%2,%3}, {%4,%5,%6,%7}, {%8,%9}, {%0,%1,%2,%3};"
        : "+f"(c[0]), "+f"(c[1]), "+f"(c[2]), "+f"(c[3])
        : "r"(a[0]), "r"(a[1]), "r"(a[2]), "r"(a[3]), "r"(b0), "r"(b1));
}

// load 128 rows x 64 fp16 (row stride ld elems) into XOR-swizzled smem tile
__device__ __forceinline__ void load_tile_h(uint32_t dst, const __half* g, int ld, int tid) {
#pragma unroll
    for (int i = 0; i < 4; i++) {
        int idx = tid + i * NTHREADS;
        int row = idx >> 3;
        int c   = idx & 7;
        uint32_t off = (uint32_t)(row << 7) | (uint32_t)(((c ^ (row & 7)) << 4));
        CP16(dst + off, g + (size_t)row * ld + (c << 3));
    }
}

// ============================================================================
// NT GEMM (fp16 in, f32 acc): C[m,n] = alpha * sum_k A[m,k]*B[n,k]
// CTA tile 128x128, 8 warps (2x4), warp tile 64x32, BK=64, 3 stages, PDL.
// (compute core byte-identical to round-6/12/13 champion)
// ============================================================================
__global__ void __launch_bounds__(NTHREADS, 2)
gemm_h(const __half* __restrict__ A, int lda, long sAb, long sAk,
       const __half* __restrict__ B, int ldb, long sBb, long sBk,
       void* __restrict__ Cv, int ldc, long sCb, long sCk,
       int Kdim, float alpha, int Kcnt, int halfOut)
{
    extern __shared__ __half smh[];
    const uint32_t smb = smem_u32(smh);

    const int tid  = threadIdx.x;
    const int wid  = tid >> 5;
    const int lane = tid & 31;
    const int gid  = lane >> 2;
    const int tg   = lane & 3;
    const int warpMoff = (wid >> 2) * 64;
    const int warpNoff = (wid & 3) * 32;

    const int z  = blockIdx.z;
    const int zb = z / Kcnt;
    const int zk = z - zb * Kcnt;
    const __half* Ab = A + (size_t)zb * sAb + (size_t)zk * sAk + (size_t)(blockIdx.y * 128) * lda;
    const __half* Bb = B + (size_t)zb * sBb + (size_t)zk * sBk + (size_t)(blockIdx.x * 128) * ldb;
    const size_t cOff = (size_t)zb * sCb + (size_t)zk * sCk
                      + (size_t)(blockIdx.y * 128) * ldc + (size_t)(blockIdx.x * 128);

    const int numK = Kdim >> 6;

    float c[4][4][4];
#pragma unroll
    for (int i = 0; i < 4; i++)
#pragma unroll
        for (int j = 0; j < 4; j++)
#pragma unroll
            for (int r = 0; r < 4; r++) c[i][j][r] = 0.0f;

    const int rlA = lane & 15;
    const int hiA = lane >> 4;
    const int rlB = ((lane >> 4) << 3) + (lane & 7);
    const int hiB = (lane >> 3) & 1;

    GDC_WAIT();   // predecessor's writes visible from here

    load_tile_h(smb,          Ab, lda, tid);
    load_tile_h(smb + TILEB,  Bb, ldb, tid);
    CP_COMMIT();
    if (numK > 1) {
        load_tile_h(smb + STAGEB,         Ab + BK, lda, tid);
        load_tile_h(smb + STAGEB + TILEB, Bb + BK, ldb, tid);
    }
    CP_COMMIT();

    int buf = 0;
    for (int kt = 0; kt < numK; kt++) {
        CP_WAIT1();
        __syncthreads();

        const int nk = kt + 2;
        if (nk < numK) {
            int nbuf = buf + 2; if (nbuf >= NSTAGE) nbuf -= NSTAGE;
            const uint32_t nbb = smb + nbuf * STAGEB;
            load_tile_h(nbb,         Ab + nk * BK, lda, tid);
            load_tile_h(nbb + TILEB, Bb + nk * BK, ldb, tid);
        }
        CP_COMMIT();

        const uint32_t At = smb + buf * STAGEB;
        const uint32_t Bt = At + TILEB;

#pragma unroll
        for (int kk = 0; kk < 4; kk++) {
            uint32_t a[4][4], bb[2][4];
            const int cA = kk * 2 + hiA;
            const int cB = kk * 2 + hiB;
#pragma unroll
            for (int i = 0; i < 4; i++) {
                const int row = warpMoff + i * 16 + rlA;
                uint32_t ad = At + ((uint32_t)row << 7)
                            + (uint32_t)(((cA ^ (row & 7)) << 4));
                LDSM4(a[i], ad);
            }
#pragma unroll
            for (int j = 0; j < 2; j++) {
                const int row = warpNoff + j * 16 + rlB;
                uint32_t bd = Bt + ((uint32_t)row << 7)
                            + (uint32_t)(((cB ^ (row & 7)) << 4));
                LDSM4(bb[j], bd);
            }
#pragma unroll
            for (int i = 0; i < 4; i++)
#pragma unroll
                for (int jj = 0; jj < 4; jj++)
                    mma_f16(c[i][jj], a[i], bb[jj >> 1][(jj & 1) * 2],
                                             bb[jj >> 1][(jj & 1) * 2 + 1]);
        }

        if (++buf == NSTAGE) buf = 0;
    }

    if (halfOut) {
        __half* Cb = (__half*)Cv + cOff;
#pragma unroll
        for (int i = 0; i < 4; i++) {
            const int r0 = warpMoff + i * 16 + gid;
#pragma unroll
            for (int jj = 0; jj < 4; jj++) {
                const int cc = warpNoff + jj * 8 + tg * 2;
                *(__half2*)(Cb + (size_t)r0 * ldc + cc) =
                    __floats2half2_rn(alpha * c[i][jj][0], alpha * c[i][jj][1]);
                *(__half2*)(Cb + (size_t)(r0 + 8) * ldc + cc) =
                    __floats2half2_rn(alpha * c[i][jj][2], alpha * c[i][jj][3]);
            }
        }
    } else {
        float* Cb = (float*)Cv + cOff;
#pragma unroll
        for (int i = 0; i < 4; i++) {
            const int r0 = warpMoff + i * 16 + gid;
#pragma unroll
            for (int jj = 0; jj < 4; jj++) {
                const int cc = warpNoff + jj * 8 + tg * 2;
                float2 v0, v1;
                v0.x = alpha * c[i][jj][0]; v0.y = alpha * c[i][jj][1];
                v1.x = alpha * c[i][jj][2]; v1.y = alpha * c[i][jj][3];
                *(float2*)(Cb + (size_t)r0 * ldc + cc)       = v0;
                *(float2*)(Cb + (size_t)(r0 + 8) * ldc + cc) = v1;
            }
        }
    }
    GDC_LAUNCH();
}

// ============================================================================
// prep_all: ONE grid for all input prep.
//   z = 0..3 : xsa batch z -> xh (fp16) + xth (fp16 transposed)
//   z = 4    : Wq -> wh (fp16), 512 blocks x 256 threads x 4 float4
// ============================================================================
__global__ void prep_all(const float* __restrict__ xsa, const float* __restrict__ Wq,
                         __half* __restrict__ xh, __half* __restrict__ xth,
                         __half* __restrict__ wh)
{
    __shared__ __half t[32][33];
    const int z = blockIdx.z;
    const int x = threadIdx.x, y = threadIdx.y;   // 32 x 8

    GDC_WAIT();   // guards against the previous graph REPLAY's readers

    if (z == 4) {
        // Wq convert: 524288 float4 over 512 blocks * 256 thr * 4
        const int blk = blockIdx.y * 32 + blockIdx.x;     // 0..511
        const int tid = y * 32 + x;
        int i = (blk * 256 + tid) * 4;
#pragma unroll
        for (int u = 0; u < 4; u++, i++) {
            float4 v = ((const float4*)Wq)[i];
            ((__half2*)wh)[2 * i]     = __floats2half2_rn(v.x, v.y);
            ((__half2*)wh)[2 * i + 1] = __floats2half2_rn(v.z, v.w);
        }
    } else {
        const int l0 = blockIdx.x * 32, e0 = blockIdx.y * 32;
        const float* in = xsa + (size_t)z * 524288;
        __half* xhb  = xh  + (size_t)z * 524288;
        __half* xthb = xth + (size_t)z * 524288;
#pragma unroll
        for (int i = 0; i < 32; i += 8) {
            __half h = __float2half_rn(in[(size_t)(l0 + y + i) * 512 + e0 + x]);
            xhb[(size_t)(l0 + y + i) * 512 + e0 + x] = h;
            t[y + i][x] = h;
        }
        __syncthreads();
#pragma unroll
        for (int i = 0; i < 32; i += 8)
            xthb[(size_t)(e0 + y + i) * 1024 + l0 + x] = t[x][y + i];
    }
    GDC_LAUNCH();
}

// ============================================================================
// softmax rows of 1024, in place (f32); also writes fp16 copy to ph. PDL.
// ============================================================================
__global__ void softmax_rows_kernel(float* __restrict__ p, __half* __restrict__ ph)
{
    __shared__ float red[32];
    const size_t roff = (size_t)blockIdx.x * 1024;
    float* row = p + roff;
    const int t = threadIdx.x;

    GDC_WAIT();   // K2's pijk writes visible from here

    float4 v = ((const float4*)row)[t];

    float m = fmaxf(fmaxf(v.x, v.y), fmaxf(v.z, v.w));
#pragma unroll
    for (int o = 16; o; o >>= 1) m = fmaxf(m, __shfl_xor_sync(0xffffffffu, m, o));
    if ((t & 31) == 0) red[t >> 5] = m;
    __syncthreads();
    if (t < 32) {
        float mm = (t < 8) ? red[t] : -CUDART_INF_F;
#pragma unroll
        for (int o = 4; o; o >>= 1) mm = fmaxf(mm, __shfl_xor_sync(0xffffffffu, mm, o));
        if (t == 0) red[0] = mm;
    }
    __syncthreads();
    m = red[0];
    __syncthreads();

    v.x = __expf(v.x - m); v.y = __expf(v.y - m);
    v.z = __expf(v.z - m); v.w = __expf(v.w - m);

    float s = v.x + v.y + v.z + v.w;
#pragma unroll
    for (int o = 16; o; o >>= 1) s += __shfl_xor_sync(0xffffffffu, s, o);
    if ((t & 31) == 0) red[t >> 5] = s;
    __syncthreads();
    if (t < 32) {
        float ss = (t < 8) ? red[t] : 0.0f;
#pragma unroll
        for (int o = 4; o; o >>= 1) ss += __shfl_xor_sync(0xffffffffu, ss, o);
        if (t == 0) red[0] = ss;
    }
    __syncthreads();
    const float inv = 1.0f / red[0];

    v.x *= inv; v.y *= inv; v.z *= inv; v.w *= inv;
    ((float4*)row)[t] = v;

    __half2* pp = (__half2*)(ph + roff);
    pp[2 * t]     = __floats2half2_rn(v.x, v.y);
    pp[2 * t + 1] = __floats2half2_rn(v.z, v.w);
    GDC_LAUNCH();
}

// ============================================================================
extern "C" void kernel_launch(void* const* d_in, const int* in_sizes, int n_in,
                              void* d_out, int out_size)
{
    (void)in_sizes; (void)n_in; (void)out_size;
    const float* xsa = (const float*)d_in[0];
    const float* Wq  = (const float*)d_in[1];
    float* out  = (float*)d_out;
    float* xid  = out;
    float* pijk = out + 16777216UL;

    __half *qh, *xh, *wh, *xth, *ph;
    cudaGetSymbolAddress((void**)&qh,  g_qh);
    cudaGetSymbolAddress((void**)&xh,  g_xh);
    cudaGetSymbolAddress((void**)&wh,  g_wh);
    cudaGetSymbolAddress((void**)&xth, g_xth);
    cudaGetSymbolAddress((void**)&ph,  g_ph);

    cudaFuncSetAttribute(gemm_h, cudaFuncAttributeMaxDynamicSharedMemorySize, DSMEMB);

    const float inv_sqrt_e = 0.044194173824159216f;

    // PDL launch config
    cudaLaunchAttribute at[1];
    at[0].id = cudaLaunchAttributeProgrammaticStreamSerialization;
    at[0].val.programmaticStreamSerializationAllowed = 1;

    cudaLaunchConfig_t cfg{};
    cfg.attrs = at;
    cfg.numAttrs = 1;
    cfg.stream = 0;

    // prep (merged: xsa convert+transpose, Wq convert)
    cfg.gridDim = dim3(32, 16, 5); cfg.blockDim = dim3(32, 8); cfg.dynamicSmemBytes = 0;
    cudaLaunchKernelEx(&cfg, prep_all, xsa, Wq, xh, xth, wh);

    // K1: q = xh @ wh^T   M=4096 N=4096 K=512, fp16 out
    cfg.gridDim = dim3(32, 32, 1); cfg.blockDim = dim3(NTHREADS); cfg.dynamicSmemBytes = DSMEMB;
    cudaLaunchKernelEx(&cfg, gemm_h,
        (const __half*)xh, 512, 0L, 0L,
        (const __half*)wh, 512, 0L, 0L,
        (void*)qh, 4096, 0L, 0L,
        512, 1.0f, 1, 1);

    // K2: logits = qh_bk @ xh_b^T / sqrt(E)   M=1024 N=1024 K=512, 32 batches
    cfg.gridDim = dim3(8, 8, 32);
    cudaLaunchKernelEx(&cfg, gemm_h,
        (const __half*)qh, 4096, 4194304L, 512L,
        (const __half*)xh, 512,  524288L,  0L,
        (void*)pijk, 8192, 8388608L, 1024L,
        512, inv_sqrt_e, 8, 0);

    // K3: softmax -> pijk f32 (output) + ph fp16 (K4 operand)
    cfg.gridDim = dim3(32768); cfg.blockDim = dim3(256); cfg.dynamicSmemBytes = 0;
    cudaLaunchKernelEx(&cfg, softmax_rows_kernel, pijk, ph);

    // K4: y = ph_bk @ xth_b^T   M=1024 N=512 K=1024, 32 batches
    cfg.gridDim = dim3(4, 8, 32); cfg.blockDim = dim3(NTHREADS); cfg.dynamicSmemBytes = DSMEMB;
    cudaLaunchKernelEx(&cfg, gemm_h,
        (const __half*)ph,  8192, 8388608L, 1024L,
        (const __half*)xth, 1024, 524288L,  0L,
        (void*)xid, 4096, 4194304L, 512L,
        1024, 1.0f, 8, 0);
}

// round 15
// speedup vs baseline: 1.0286x; 1.0286x over previous
#include <cuda_runtime.h>
#include <cuda_fp16.h>
#include <cstdint>
#include <math_constants.h>

// ============================================================================
// QKV_Attention via mma.sync m16n8k16 fp16 (f32 acc) + ldmatrix. PDL graph.
// Round 15: K2 writes fp16 logits (64MB) instead of f32 (128MB); softmax
// reads fp16 logits, computes f32, writes pijk f32 (output) and overwrites
// the logit buffer in place with fp16 probabilities for K4.
// K2->softmax path traffic: 448MB -> 320MB.
// ============================================================================

#define NTHREADS 256
#define BK 64
#define TILEB 16384                 // 128 rows x 128B
#define STAGEB (2*TILEB)            // A + B
#define NSTAGE 3
#define DSMEMB (NSTAGE*STAGEB)      // 98304

__device__ __half g_qh [4096UL*4096UL];      // 32 MB
__device__ __half g_xh [4UL*1024UL*512UL];   //  4 MB
__device__ __half g_wh [4096UL*512UL];       //  4 MB
__device__ __half g_xth[4UL*512UL*1024UL];   //  4 MB
__device__ __half g_ph [32768UL*1024UL];     // 64 MB (logits in, probs out)

// ---------------------------------------------------------------- helpers
#define GDC_WAIT()   asm volatile("griddepcontrol.wait;" ::: "memory")
#define GDC_LAUNCH() asm volatile("griddepcontrol.launch_dependents;" ::: "memory")

__device__ __forceinline__ uint32_t smem_u32(const void* p) {
    uint32_t a;
    asm("{ .reg .u64 t; cvta.to.shared.u64 t, %1; cvt.u32.u64 %0, t; }"
        : "=r"(a) : "l"(p));
    return a;
}
#define CP16(d, s) \
    asm volatile("cp.async.cg.shared.global [%0], [%1], 16;" :: "r"(d), "l"(s))
#define CP_COMMIT() asm volatile("cp.async.commit_group;" ::: "memory")
#define CP_WAIT1()  asm volatile("cp.async.wait_group 1;" ::: "memory")

#define LDSM4(r, a) \
    asm volatile("ldmatrix.sync.aligned.m8n8.x4.shared.b16 {%0,%1,%2,%3}, [%4];" \
        : "=r"((r)[0]), "=r"((r)[1]), "=r"((r)[2]), "=r"((r)[3]) : "r"(a))

__device__ __forceinline__ void mma_f16(float c[4], const uint32_t a[4],
                                        uint32_t b0, uint32_t b1) {
    asm volatile(
        "mma.sync.aligned.m16n8k16.row.col.f32.f16.f16.f32 "
        "{%0,%1,%2,%3}, {%4,%5,%6,%7}, {%8,%9}, {%0,%1,%2,%3};"
        : "+f"(c[0]), "+f"(c[1]), "+f"(c[2]), "+f"(c[3])
        : "r"(a[0]), "r"(a[1]), "r"(a[2]), "r"(a[3]), "r"(b0), "r"(b1));
}

// load 128 rows x 64 fp16 (row stride ld elems) into XOR-swizzled smem tile
__device__ __forceinline__ void load_tile_h(uint32_t dst, const __half* g, int ld, int tid) {
#pragma unroll
    for (int i = 0; i < 4; i++) {
        int idx = tid + i * NTHREADS;
        int row = idx >> 3;
        int c   = idx & 7;
        uint32_t off = (uint32_t)(row << 7) | (uint32_t)(((c ^ (row & 7)) << 4));
        CP16(dst + off, g + (size_t)row * ld + (c << 3));
    }
}

// ============================================================================
// NT GEMM (fp16 in, f32 acc): C[m,n] = alpha * sum_k A[m,k]*B[n,k]
// CTA tile 128x128, 8 warps (2x4), warp tile 64x32, BK=64, 3 stages, PDL.
// ============================================================================
__global__ void __launch_bounds__(NTHREADS, 2)
gemm_h(const __half* __restrict__ A, int lda, long sAb, long sAk,
       const __half* __restrict__ B, int ldb, long sBb, long sBk,
       void* __restrict__ Cv, int ldc, long sCb, long sCk,
       int Kdim, float alpha, int Kcnt, int halfOut)
{
    extern __shared__ __half smh[];
    const uint32_t smb = smem_u32(smh);

    const int tid  = threadIdx.x;
    const int wid  = tid >> 5;
    const int lane = tid & 31;
    const int gid  = lane >> 2;
    const int tg   = lane & 3;
    const int warpMoff = (wid >> 2) * 64;
    const int warpNoff = (wid & 3) * 32;

    const int z  = blockIdx.z;
    const int zb = z / Kcnt;
    const int zk = z - zb * Kcnt;
    const __half* Ab = A + (size_t)zb * sAb + (size_t)zk * sAk + (size_t)(blockIdx.y * 128) * lda;
    const __half* Bb = B + (size_t)zb * sBb + (size_t)zk * sBk + (size_t)(blockIdx.x * 128) * ldb;
    const size_t cOff = (size_t)zb * sCb + (size_t)zk * sCk
                      + (size_t)(blockIdx.y * 128) * ldc + (size_t)(blockIdx.x * 128);

    const int numK = Kdim >> 6;

    float c[4][4][4];
#pragma unroll
    for (int i = 0; i < 4; i++)
#pragma unroll
        for (int j = 0; j < 4; j++)
#pragma unroll
            for (int r = 0; r < 4; r++) c[i][j][r] = 0.0f;

    const int rlA = lane & 15;
    const int hiA = lane >> 4;
    const int rlB = ((lane >> 4) << 3) + (lane & 7);
    const int hiB = (lane >> 3) & 1;

    GDC_WAIT();

    load_tile_h(smb,          Ab, lda, tid);
    load_tile_h(smb + TILEB,  Bb, ldb, tid);
    CP_COMMIT();
    if (numK > 1) {
        load_tile_h(smb + STAGEB,         Ab + BK, lda, tid);
        load_tile_h(smb + STAGEB + TILEB, Bb + BK, ldb, tid);
    }
    CP_COMMIT();

    int buf = 0;
    for (int kt = 0; kt < numK; kt++) {
        CP_WAIT1();
        __syncthreads();

        const int nk = kt + 2;
        if (nk < numK) {
            int nbuf = buf + 2; if (nbuf >= NSTAGE) nbuf -= NSTAGE;
            const uint32_t nbb = smb + nbuf * STAGEB;
            load_tile_h(nbb,         Ab + nk * BK, lda, tid);
            load_tile_h(nbb + TILEB, Bb + nk * BK, ldb, tid);
        }
        CP_COMMIT();

        const uint32_t At = smb + buf * STAGEB;
        const uint32_t Bt = At + TILEB;

#pragma unroll
        for (int kk = 0; kk < 4; kk++) {
            uint32_t a[4][4], bb[2][4];
            const int cA = kk * 2 + hiA;
            const int cB = kk * 2 + hiB;
#pragma unroll
            for (int i = 0; i < 4; i++) {
                const int row = warpMoff + i * 16 + rlA;
                uint32_t ad = At + ((uint32_t)row << 7)
                            + (uint32_t)(((cA ^ (row & 7)) << 4));
                LDSM4(a[i], ad);
            }
#pragma unroll
            for (int j = 0; j < 2; j++) {
                const int row = warpNoff + j * 16 + rlB;
                uint32_t bd = Bt + ((uint32_t)row << 7)
                            + (uint32_t)(((cB ^ (row & 7)) << 4));
                LDSM4(bb[j], bd);
            }
#pragma unroll
            for (int i = 0; i < 4; i++)
#pragma unroll
                for (int jj = 0; jj < 4; jj++)
                    mma_f16(c[i][jj], a[i], bb[jj >> 1][(jj & 1) * 2],
                                             bb[jj >> 1][(jj & 1) * 2 + 1]);
        }

        if (++buf == NSTAGE) buf = 0;
    }

    if (halfOut) {
        __half* Cb = (__half*)Cv + cOff;
#pragma unroll
        for (int i = 0; i < 4; i++) {
            const int r0 = warpMoff + i * 16 + gid;
#pragma unroll
            for (int jj = 0; jj < 4; jj++) {
                const int cc = warpNoff + jj * 8 + tg * 2;
                *(__half2*)(Cb + (size_t)r0 * ldc + cc) =
                    __floats2half2_rn(alpha * c[i][jj][0], alpha * c[i][jj][1]);
                *(__half2*)(Cb + (size_t)(r0 + 8) * ldc + cc) =
                    __floats2half2_rn(alpha * c[i][jj][2], alpha * c[i][jj][3]);
            }
        }
    } else {
        float* Cb = (float*)Cv + cOff;
#pragma unroll
        for (int i = 0; i < 4; i++) {
            const int r0 = warpMoff + i * 16 + gid;
#pragma unroll
            for (int jj = 0; jj < 4; jj++) {
                const int cc = warpNoff + jj * 8 + tg * 2;
                float2 v0, v1;
                v0.x = alpha * c[i][jj][0]; v0.y = alpha * c[i][jj][1];
                v1.x = alpha * c[i][jj][2]; v1.y = alpha * c[i][jj][3];
                *(float2*)(Cb + (size_t)r0 * ldc + cc)       = v0;
                *(float2*)(Cb + (size_t)(r0 + 8) * ldc + cc) = v1;
            }
        }
    }
    GDC_LAUNCH();
}

// ============================================================================
// prep_x: one pass over xsa -> xh (fp16) AND xth (fp16 transposed). PDL.
// ============================================================================
__global__ void prep_x(const float* __restrict__ in,
                       __half* __restrict__ xh, __half* __restrict__ xth)
{
    __shared__ __half t[32][33];
    const int b = blockIdx.z;
    const int l0 = blockIdx.x * 32, e0 = blockIdx.y * 32;
    in  += (size_t)b * 524288;
    xh  += (size_t)b * 524288;
    xth += (size_t)b * 524288;
    const int x = threadIdx.x, y = threadIdx.y;
    GDC_WAIT();   // previous graph replay's readers
#pragma unroll
    for (int i = 0; i < 32; i += 8) {
        __half h = __float2half_rn(in[(size_t)(l0 + y + i) * 512 + e0 + x]);
        xh[(size_t)(l0 + y + i) * 512 + e0 + x] = h;
        t[y + i][x] = h;
    }
    __syncthreads();
#pragma unroll
    for (int i = 0; i < 32; i += 8)
        xth[(size_t)(e0 + y + i) * 1024 + l0 + x] = t[x][y + i];
    GDC_LAUNCH();
}

// cvt_w: Wq f32 -> fp16. PDL.
__global__ void cvt_w(const float* __restrict__ in, __half* __restrict__ out)
{
    int i = blockIdx.x * blockDim.x + threadIdx.x;
    GDC_WAIT();
    float4 v = ((const float4*)in)[i];
    ((__half2*)out)[2 * i]     = __floats2half2_rn(v.x, v.y);
    ((__half2*)out)[2 * i + 1] = __floats2half2_rn(v.z, v.w);
    GDC_LAUNCH();
}

// ============================================================================
// softmax: reads fp16 logits from ph, computes f32 softmax,
// writes pijk f32 (output) and overwrites ph with fp16 probabilities (K4
// operand). One 256-thread block per row of 1024; 4 elements/thread.
// ============================================================================
__global__ void softmax_rows_kernel(float* __restrict__ p, __half* __restrict__ ph)
{
    __shared__ float red[32];
    const size_t roff = (size_t)blockIdx.x * 1024;
    const int t = threadIdx.x;

    GDC_WAIT();   // K2's logit writes visible from here

    __half2* rowh = (__half2*)(ph + roff);
    // load 4 fp16 logits
    uint2 raw = ((const uint2*)rowh)[t];
    float2 lo = __half22float2(*(__half2*)&raw.x);
    float2 hi = __half22float2(*(__half2*)&raw.y);
    float4 v = make_float4(lo.x, lo.y, hi.x, hi.y);

    float m = fmaxf(fmaxf(v.x, v.y), fmaxf(v.z, v.w));
#pragma unroll
    for (int o = 16; o; o >>= 1) m = fmaxf(m, __shfl_xor_sync(0xffffffffu, m, o));
    if ((t & 31) == 0) red[t >> 5] = m;
    __syncthreads();
    if (t < 32) {
        float mm = (t < 8) ? red[t] : -CUDART_INF_F;
#pragma unroll
        for (int o = 4; o; o >>= 1) mm = fmaxf(mm, __shfl_xor_sync(0xffffffffu, mm, o));
        if (t == 0) red[0] = mm;
    }
    __syncthreads();
    m = red[0];
    __syncthreads();

    v.x = __expf(v.x - m); v.y = __expf(v.y - m);
    v.z = __expf(v.z - m); v.w = __expf(v.w - m);

    float s = v.x + v.y + v.z + v.w;
#pragma unroll
    for (int o = 16; o; o >>= 1) s += __shfl_xor_sync(0xffffffffu, s, o);
    if ((t & 31) == 0) red[t >> 5] = s;
    __syncthreads();
    if (t < 32) {
        float ss = (t < 8) ? red[t] : 0.0f;
#pragma unroll
        for (int o = 4; o; o >>= 1) ss += __shfl_xor_sync(0xffffffffu, ss, o);
        if (t == 0) red[0] = ss;
    }
    __syncthreads();
    const float inv = 1.0f / red[0];

    v.x *= inv; v.y *= inv; v.z *= inv; v.w *= inv;

    // pijk f32 output
    ((float4*)(p + roff))[t] = v;
    // overwrite logits with fp16 probabilities (K4 operand)
    uint2 wb;
    *(__half2*)&wb.x = __floats2half2_rn(v.x, v.y);
    *(__half2*)&wb.y = __floats2half2_rn(v.z, v.w);
    ((uint2*)rowh)[t] = wb;

    GDC_LAUNCH();
}

// ============================================================================
extern "C" void kernel_launch(void* const* d_in, const int* in_sizes, int n_in,
                              void* d_out, int out_size)
{
    (void)in_sizes; (void)n_in; (void)out_size;
    const float* xsa = (const float*)d_in[0];
    const float* Wq  = (const float*)d_in[1];
    float* out  = (float*)d_out;
    float* xid  = out;
    float* pijk = out + 16777216UL;

    __half *qh, *xh, *wh, *xth, *ph;
    cudaGetSymbolAddress((void**)&qh,  g_qh);
    cudaGetSymbolAddress((void**)&xh,  g_xh);
    cudaGetSymbolAddress((void**)&wh,  g_wh);
    cudaGetSymbolAddress((void**)&xth, g_xth);
    cudaGetSymbolAddress((void**)&ph,  g_ph);

    cudaFuncSetAttribute(gemm_h, cudaFuncAttributeMaxDynamicSharedMemorySize, DSMEMB);

    const float inv_sqrt_e = 0.044194173824159216f;

    // PDL launch config
    cudaLaunchAttribute at[1];
    at[0].id = cudaLaunchAttributeProgrammaticStreamSerialization;
    at[0].val.programmaticStreamSerializationAllowed = 1;

    cudaLaunchConfig_t cfg{};
    cfg.attrs = at;
    cfg.numAttrs = 1;
    cfg.stream = 0;

    // prep
    cfg.gridDim = dim3(32, 16, 4); cfg.blockDim = dim3(32, 8); cfg.dynamicSmemBytes = 0;
    cudaLaunchKernelEx(&cfg, prep_x, xsa, xh, xth);

    cfg.gridDim = dim3(2048); cfg.blockDim = dim3(256); cfg.dynamicSmemBytes = 0;
    cudaLaunchKernelEx(&cfg, cvt_w, Wq, wh);

    // K1: q = xh @ wh^T   M=4096 N=4096 K=512, fp16 out
    cfg.gridDim = dim3(32, 32, 1); cfg.blockDim = dim3(NTHREADS); cfg.dynamicSmemBytes = DSMEMB;
    cudaLaunchKernelEx(&cfg, gemm_h,
        (const __half*)xh, 512, 0L, 0L,
        (const __half*)wh, 512, 0L, 0L,
        (void*)qh, 4096, 0L, 0L,
        512, 1.0f, 1, 1);

    // K2: logits (fp16!) = qh_bk @ xh_b^T / sqrt(E) -> ph   M=1024 N=1024 K=512
    cfg.gridDim = dim3(8, 8, 32);
    cudaLaunchKernelEx(&cfg, gemm_h,
        (const __half*)qh, 4096, 4194304L, 512L,
        (const __half*)xh, 512,  524288L,  0L,
        (void*)ph, 8192, 8388608L, 1024L,
        512, inv_sqrt_e, 8, 1);

    // K3: softmax: ph(logits fp16) -> pijk f32 + ph(probs fp16, in place)
    cfg.gridDim = dim3(32768); cfg.blockDim = dim3(256); cfg.dynamicSmemBytes = 0;
    cudaLaunchKernelEx(&cfg, softmax_rows_kernel, pijk, ph);

    // K4: y = ph_bk @ xth_b^T   M=1024 N=512 K=1024, 32 batches
    cfg.gridDim = dim3(4, 8, 32); cfg.blockDim = dim3(NTHREADS); cfg.dynamicSmemBytes = DSMEMB;
    cudaLaunchKernelEx(&cfg, gemm_h,
        (const __half*)ph,  8192, 8388608L, 1024L,
        (const __half*)xth, 1024, 524288L,  0L,
        (void*)xid, 4096, 4194304L, 512L,
        1024, 1.0f, 8, 0);
}